// round 2
// baseline (speedup 1.0000x reference)
#include <cuda_runtime.h>
#include <math.h>

#define Bb 4
#define Ss 1024
#define Dd 512
#define Hh 8
#define DHd 64

__device__ __constant__ float kScale = 0.044194173824159216f; // 1/sqrt(512)

// scratch: 11 chunks of B*S*D floats
#define CHUNK ((size_t)Bb * Ss * Dd)  // 2097152
__device__ float g_scratch[CHUNK * 11];

#define OFF_QU1 (0 * CHUNK)
#define OFF_QV1 (1 * CHUNK)
#define OFF_K1  (2 * CHUNK)
#define OFF_V1  (3 * CHUNK)
#define OFF_QU2 (4 * CHUNK)
#define OFF_QV2 (5 * CHUNK)
#define OFF_K2  (6 * CHUNK)
#define OFF_V2  (7 * CHUNK)
#define OFF_POS (8 * CHUNK)
#define OFF_CTX1 (9 * CHUNK)
#define OFF_CTX2 (10 * CHUNK)

// d_out offsets (floats)
#define OFF_CTX1OUT ((size_t)0)
#define OFF_ATTN1   ((size_t)2097152)
#define OFF_CTX2OUT ((size_t)35651584)
#define OFF_ATTN2   ((size_t)37748736)

// ---------------------------------------------------------------------------
// SGEMM: C[4096,512] = A[4096,512] @ W[512,512] (+bias), epilogue modes:
//   mode 0: dst0[gr*512+gc] = v                         (row-major)
//   mode 1: head-major scatter to [B,H,S,DH]
//   mode 2: like 1, but two outputs with extra biases (q+u, q+v)
// ---------------------------------------------------------------------------
__global__ __launch_bounds__(256)
void sgemm_kernel(const float* __restrict__ A, const float* __restrict__ W,
                  const float* __restrict__ bias,
                  float* __restrict__ dst0, float* __restrict__ dst1,
                  const float* __restrict__ eb0, const float* __restrict__ eb1,
                  int mode)
{
    __shared__ float As[8][128];
    __shared__ float Bs[8][128];
    int tid = threadIdx.x;
    int tx = tid & 15, ty = tid >> 4;
    int bx = blockIdx.x, by = blockIdx.y;

    float acc[8][8];
#pragma unroll
    for (int i = 0; i < 8; i++)
#pragma unroll
        for (int j = 0; j < 8; j++) acc[i][j] = 0.f;

    int arow = tid >> 1, ahalf = tid & 1;
    int bkr = tid >> 5, bn = tid & 31;
    const float* Aptr = A + (size_t)(by * 128 + arow) * 512 + ahalf * 4;
    const float* Wptr = W + (size_t)bkr * 512 + bx * 128 + bn * 4;

    for (int kk = 0; kk < 64; kk++) {
        float4 av = *(const float4*)(Aptr + kk * 8);
        As[ahalf * 4 + 0][arow] = av.x;
        As[ahalf * 4 + 1][arow] = av.y;
        As[ahalf * 4 + 2][arow] = av.z;
        As[ahalf * 4 + 3][arow] = av.w;
        float4 wv = *(const float4*)(Wptr + (size_t)kk * 8 * 512);
        *(float4*)&Bs[bkr][bn * 4] = wv;
        __syncthreads();
#pragma unroll
        for (int k = 0; k < 8; k++) {
            float4 a0 = *(const float4*)&As[k][ty * 8];
            float4 a1 = *(const float4*)&As[k][ty * 8 + 4];
            float4 b0 = *(const float4*)&Bs[k][tx * 8];
            float4 b1 = *(const float4*)&Bs[k][tx * 8 + 4];
            float ar[8] = {a0.x, a0.y, a0.z, a0.w, a1.x, a1.y, a1.z, a1.w};
            float br[8] = {b0.x, b0.y, b0.z, b0.w, b1.x, b1.y, b1.z, b1.w};
#pragma unroll
            for (int i = 0; i < 8; i++)
#pragma unroll
                for (int j = 0; j < 8; j++) acc[i][j] += ar[i] * br[j];
        }
        __syncthreads();
    }

#pragma unroll
    for (int i = 0; i < 8; i++) {
        int gr = by * 128 + ty * 8 + i;
#pragma unroll
        for (int j = 0; j < 8; j++) {
            int gc = bx * 128 + tx * 8 + j;
            float v = acc[i][j] + (bias ? bias[gc] : 0.f);
            if (mode == 0) {
                dst0[(size_t)gr * 512 + gc] = v;
            } else {
                int h = gc >> 6, d = gc & 63;
                int bI = gr >> 10, sI = gr & 1023;
                size_t off = (((size_t)(bI * Hh + h) * Ss + sI) * DHd + d);
                if (mode == 1) {
                    dst0[off] = v;
                } else {
                    dst0[off] = v + eb0[gc];
                    dst1[off] = v + eb1[gc];
                }
            }
        }
    }
}

// ---------------------------------------------------------------------------
// Fused attention kernel: per block = 16 query rows of one (b, h, stream).
// Phases: load QU/QV/mask -> content scores (regs) -> pos-raw (smem, 17 rows)
//         -> rel-shift gather + mask + softmax -> write attn (gmem+smem)
//         -> ctx = attn @ V -> write ctx scratch.
// ---------------------------------------------------------------------------
__global__ __launch_bounds__(256)
void attn_kernel(float* __restrict__ scratch,
                 const unsigned char* __restrict__ maskg,
                 float* __restrict__ out)
{
    extern __shared__ float sm[];
    float* qu   = sm;                 // 16*64   = 1024 floats
    float* qv   = sm + 1024;          // 17*64   = 1088 floats
    float* kbuf = sm + 2112;          // 128*68  = 8704 floats
    float* praw = sm + 10816;         // 17*1024 = 17408 floats (reused as attn tile)
    unsigned char* msk = (unsigned char*)(sm + 28224); // 1024 bytes

    int tid = threadIdx.x;
    int lane = tid & 31, w = tid >> 5;
    int tile = blockIdx.x;   // 0..63
    int h = blockIdx.y;      // 0..7
    int bz = blockIdx.z;     // 0..7
    int b = bz >> 1, st = bz & 1;

    const float* QUg = scratch + (st ? OFF_QU2 : OFF_QU1);
    const float* QVg = scratch + (st ? OFF_QV2 : OFF_QV1);
    const float* Kg  = scratch + (st ? OFF_K2  : OFF_K1);
    const float* Vg  = scratch + (st ? OFF_V2  : OFF_V1);
    const float* Pg  = scratch + OFF_POS;
    float* CTXg = scratch + (st ? OFF_CTX2 : OFF_CTX1);

    size_t bh = (size_t)(b * Hh + h) * Ss * DHd;

    // ---- phase 0: cooperative loads ----
#pragma unroll
    for (int it = 0; it < 4; it++) {
        int idx = it * 256 + tid;                // 0..1023
        int r = idx >> 6, d = idx & 63;
        qu[idx] = QUg[bh + (size_t)(tile * 16 + r) * 64 + d];
    }
#pragma unroll
    for (int it = 0; it < 5; it++) {
        int idx = it * 256 + tid;
        if (idx < 1088) {
            int r = idx >> 6, d = idx & 63;
            int gi = tile * 16 + r;
            if (gi > Ss - 1) gi = Ss - 1;        // row 16 of last tile is never used
            qv[idx] = QVg[bh + (size_t)gi * 64 + d];
        }
    }
    {
        const unsigned char* mrow = maskg + (size_t)b * Ss;
#pragma unroll
        for (int it = 0; it < 4; it++) {
            int idx = it * 256 + tid;
            msk[idx] = mrow[idx];
        }
    }
    __syncthreads();

    int r0 = 2 * w, r1 = 2 * w + 1;
    int ig0 = tile * 16 + r0, ig1 = ig0 + 1;
    float s0[32], s1[32];

    // ---- phase A: content scores (q+u)·k ----
#pragma unroll
    for (int c = 0; c < 8; c++) {
#pragma unroll
        for (int it = 0; it < 8; it++) {
            int q = it * 256 + tid;
            int tl = q >> 4, dseg = q & 15;
            float4 vv = *(const float4*)(Kg + bh + (size_t)(c * 128 + tl) * 64 + dseg * 4);
            float* dp = kbuf + tl * 68 + dseg * 4;
            dp[0] = vv.x; dp[1] = vv.y; dp[2] = vv.z; dp[3] = vv.w;
        }
        __syncthreads();
        const float4* u0p = (const float4*)(qu + r0 * 64);
        const float4* u1p = (const float4*)(qu + r1 * 64);
#pragma unroll
        for (int j = 0; j < 4; j++) {
            const float4* kr = (const float4*)(kbuf + (j * 32 + lane) * 68);
            float a0 = 0.f, a1 = 0.f;
#pragma unroll
            for (int d4 = 0; d4 < 16; d4++) {
                float4 k4 = kr[d4];
                float4 u0 = u0p[d4];
                float4 u1 = u1p[d4];
                a0 += u0.x * k4.x; a0 += u0.y * k4.y; a0 += u0.z * k4.z; a0 += u0.w * k4.w;
                a1 += u1.x * k4.x; a1 += u1.y * k4.y; a1 += u1.z * k4.z; a1 += u1.w * k4.w;
            }
            s0[c * 4 + j] = a0;
            s1[c * 4 + j] = a1;
        }
        __syncthreads();
    }

    // ---- phase B: pos-raw scores (q+v)·pos for 17 rows into smem ----
#pragma unroll
    for (int c = 0; c < 8; c++) {
#pragma unroll
        for (int it = 0; it < 8; it++) {
            int q = it * 256 + tid;
            int tl = q >> 4, dseg = q & 15;
            float4 vv = *(const float4*)(Pg + bh + (size_t)(c * 128 + tl) * 64 + dseg * 4);
            float* dp = kbuf + tl * 68 + dseg * 4;
            dp[0] = vv.x; dp[1] = vv.y; dp[2] = vv.z; dp[3] = vv.w;
        }
        __syncthreads();
#pragma unroll
        for (int rs = 0; rs < 3; rs++) {
            int rr;
            if (rs == 0) rr = w;
            else if (rs == 1) rr = w + 8;
            else { if (w != 0) continue; rr = 16; }
            const float4* qvp = (const float4*)(qv + rr * 64);
#pragma unroll
            for (int j = 0; j < 4; j++) {
                int tt = j * 32 + lane;
                const float4* kr = (const float4*)(kbuf + tt * 68);
                float a = 0.f;
#pragma unroll
                for (int d4 = 0; d4 < 16; d4++) {
                    float4 k4 = kr[d4];
                    float4 qq = qvp[d4];
                    a += qq.x * k4.x; a += qq.y * k4.y; a += qq.z * k4.z; a += qq.w * k4.w;
                }
                praw[rr * 1024 + c * 128 + tt] = a;
            }
        }
        __syncthreads();
    }

    // ---- phase C: rel-shift gather + mask + scale + softmax ----
    // shifted[i,t] = praw[i, S-1-i+t]  (t <= i)
    //             = 0                  (t == i+1)
    //             = praw[i+1, t-i-2]   (t >  i+1)
    float mx0 = -1e30f, mx1 = -1e30f;
#pragma unroll
    for (int jp = 0; jp < 32; jp++) {
        int t = jp * 32 + lane;
        float pv0, pv1;
        if (t <= ig0)           pv0 = praw[r0 * 1024 + (Ss - 1 - ig0 + t)];
        else if (t == ig0 + 1)  pv0 = 0.f;
        else                    pv0 = praw[(r0 + 1) * 1024 + (t - ig0 - 2)];
        if (t <= ig1)           pv1 = praw[r1 * 1024 + (Ss - 1 - ig1 + t)];
        else if (t == ig1 + 1)  pv1 = 0.f;
        else                    pv1 = praw[(r1 + 1) * 1024 + (t - ig1 - 2)];
        float sc0 = (s0[jp] + pv0) * kScale;
        float sc1 = (s1[jp] + pv1) * kScale;
        if (msk[t]) { sc0 = -1e9f; sc1 = -1e9f; }
        s0[jp] = sc0; s1[jp] = sc1;
        mx0 = fmaxf(mx0, sc0);
        mx1 = fmaxf(mx1, sc1);
    }
#pragma unroll
    for (int o = 16; o > 0; o >>= 1) {
        mx0 = fmaxf(mx0, __shfl_xor_sync(0xffffffffu, mx0, o));
        mx1 = fmaxf(mx1, __shfl_xor_sync(0xffffffffu, mx1, o));
    }
    float sum0 = 0.f, sum1 = 0.f;
#pragma unroll
    for (int jp = 0; jp < 32; jp++) {
        float e0 = __expf(s0[jp] - mx0); s0[jp] = e0; sum0 += e0;
        float e1 = __expf(s1[jp] - mx1); s1[jp] = e1; sum1 += e1;
    }
#pragma unroll
    for (int o = 16; o > 0; o >>= 1) {
        sum0 += __shfl_xor_sync(0xffffffffu, sum0, o);
        sum1 += __shfl_xor_sync(0xffffffffu, sum1, o);
    }
    float inv0 = 1.f / sum0, inv1 = 1.f / sum1;

    __syncthreads();   // all praw reads done before we overwrite it with attn

    // ---- phase D: write normalized attn to gmem and smem ----
    size_t aout = (st ? OFF_ATTN2 : OFF_ATTN1) + ((size_t)(b * Hh + h) * Ss) * Ss;
#pragma unroll
    for (int jp = 0; jp < 32; jp++) {
        int t = jp * 32 + lane;
        float p0 = s0[jp] * inv0;
        float p1 = s1[jp] * inv1;
        praw[r0 * 1024 + t] = p0;
        praw[r1 * 1024 + t] = p1;
        out[aout + (size_t)ig0 * Ss + t] = p0;
        out[aout + (size_t)ig1 * Ss + t] = p1;
    }
    __syncthreads();

    // ---- phase E: ctx = attn @ V ----
    int d = tid & 63, rbase = tid >> 6;   // 64 d-lanes x 4 row-groups
    float acc[4] = {0.f, 0.f, 0.f, 0.f};
#pragma unroll
    for (int c = 0; c < 8; c++) {
#pragma unroll
        for (int it = 0; it < 8; it++) {
            int q = it * 256 + tid;
            int tl = q >> 4, dseg = q & 15;
            float4 vv = *(const float4*)(Vg + bh + (size_t)(c * 128 + tl) * 64 + dseg * 4);
            float* dp = kbuf + tl * 68 + dseg * 4;
            dp[0] = vv.x; dp[1] = vv.y; dp[2] = vv.z; dp[3] = vv.w;
        }
        __syncthreads();
#pragma unroll
        for (int t4 = 0; t4 < 32; t4++) {
            float k0 = kbuf[(t4 * 4 + 0) * 68 + d];
            float k1 = kbuf[(t4 * 4 + 1) * 68 + d];
            float k2 = kbuf[(t4 * 4 + 2) * 68 + d];
            float k3 = kbuf[(t4 * 4 + 3) * 68 + d];
#pragma unroll
            for (int rp = 0; rp < 4; rp++) {
                int row = rp * 4 + rbase;
                float4 a = *(const float4*)(praw + row * 1024 + c * 128 + t4 * 4);
                acc[rp] += a.x * k0 + a.y * k1 + a.z * k2 + a.w * k3;
            }
        }
        __syncthreads();
    }
#pragma unroll
    for (int rp = 0; rp < 4; rp++) {
        int row = rp * 4 + rbase;
        int gi = tile * 16 + row;
        CTXg[((size_t)(b * Ss + gi)) * Dd + h * DHd + d] = acc[rp];
    }
}

// ---------------------------------------------------------------------------
extern "C" void kernel_launch(void* const* d_in, const int* in_sizes, int n_in,
                              void* d_out, int out_size)
{
    const float* x1  = (const float*)d_in[0];
    const float* x2  = (const float*)d_in[1];
    const float* pe  = (const float*)d_in[2];
    const unsigned char* mask = (const unsigned char*)d_in[3];
    const float* Wq  = (const float*)d_in[4];
    const float* bq  = (const float*)d_in[5];
    const float* Wk  = (const float*)d_in[6];
    const float* bk  = (const float*)d_in[7];
    const float* Wv  = (const float*)d_in[8];
    const float* bv  = (const float*)d_in[9];
    const float* Wp  = (const float*)d_in[10];
    const float* ub  = (const float*)d_in[11];
    const float* vb  = (const float*)d_in[12];
    const float* Wo1 = (const float*)d_in[13];
    const float* bo1 = (const float*)d_in[14];
    const float* Wo2 = (const float*)d_in[15];
    const float* bo2 = (const float*)d_in[16];
    float* out = (float*)d_out;

    float* scratch = nullptr;
    cudaGetSymbolAddress((void**)&scratch, g_scratch);

    const int attn_smem = 28480 * 4;  // 113,920 B
    cudaFuncSetAttribute(attn_kernel, cudaFuncAttributeMaxDynamicSharedMemorySize,
                         attn_smem);

    dim3 gg(4, 32);

    // projections (streams share Wq/Wk/Wv; value_proj_1 used for both streams)
    sgemm_kernel<<<gg, 256>>>(x1, Wq, bq, scratch + OFF_QU1, scratch + OFF_QV1, ub, vb, 2);
    sgemm_kernel<<<gg, 256>>>(x1, Wk, bk, scratch + OFF_K1, nullptr, nullptr, nullptr, 1);
    sgemm_kernel<<<gg, 256>>>(x1, Wv, bv, scratch + OFF_V1, nullptr, nullptr, nullptr, 1);
    sgemm_kernel<<<gg, 256>>>(x2, Wq, bq, scratch + OFF_QU2, scratch + OFF_QV2, ub, vb, 2);
    sgemm_kernel<<<gg, 256>>>(x2, Wk, bk, scratch + OFF_K2, nullptr, nullptr, nullptr, 1);
    sgemm_kernel<<<gg, 256>>>(x2, Wv, bv, scratch + OFF_V2, nullptr, nullptr, nullptr, 1);
    sgemm_kernel<<<gg, 256>>>(pe, Wp, nullptr, scratch + OFF_POS, nullptr, nullptr, nullptr, 1);

    // fused attention: scores + rel-shift + softmax + attn-out + ctx
    attn_kernel<<<dim3(64, 8, 8), 256, attn_smem>>>(scratch, mask, out);

    // output projections
    sgemm_kernel<<<gg, 256>>>(scratch + OFF_CTX1, Wo1, bo1, out + OFF_CTX1OUT,
                              nullptr, nullptr, nullptr, 0);
    sgemm_kernel<<<gg, 256>>>(scratch + OFF_CTX2, Wo2, bo2, out + OFF_CTX2OUT,
                              nullptr, nullptr, nullptr, 0);
}

// round 3
// speedup vs baseline: 1.1121x; 1.1121x over previous
#include <cuda_runtime.h>
#include <math.h>

#define Bb 4
#define Ss 1024
#define Dd 512
#define Hh 8
#define DHd 64

typedef unsigned long long ull;

__device__ __constant__ float kScale = 0.044194173824159216f; // 1/sqrt(512)

// ---- packed f32x2 helpers (sm_100+/sm_103a) ----
__device__ __forceinline__ ull pk2(float x, float y) {
    ull r; asm("mov.b64 %0, {%1, %2};" : "=l"(r) : "f"(x), "f"(y)); return r;
}
__device__ __forceinline__ ull splat2(float x) { return pk2(x, x); }
__device__ __forceinline__ float lo2(ull v) { return __uint_as_float((unsigned)v); }
__device__ __forceinline__ float hi2(ull v) { return __uint_as_float((unsigned)(v >> 32)); }
__device__ __forceinline__ void fma2(ull& d, ull a, ull b) {
    asm("fma.rn.f32x2 %0, %1, %2, %0;" : "+l"(d) : "l"(a), "l"(b));
}
__device__ __forceinline__ float red2(ull v) { return lo2(v) + hi2(v); }

// scratch: 11 chunks of B*S*D floats
#define CHUNK ((size_t)Bb * Ss * Dd)  // 2097152
__device__ float g_scratch[CHUNK * 11];

#define OFF_QU1 (0 * CHUNK)
#define OFF_QV1 (1 * CHUNK)
#define OFF_K1  (2 * CHUNK)
#define OFF_V1  (3 * CHUNK)
#define OFF_QU2 (4 * CHUNK)
#define OFF_QV2 (5 * CHUNK)
#define OFF_K2  (6 * CHUNK)
#define OFF_V2  (7 * CHUNK)
#define OFF_POS (8 * CHUNK)
#define OFF_CTX1 (9 * CHUNK)
#define OFF_CTX2 (10 * CHUNK)

// d_out offsets (floats)
#define OFF_CTX1OUT ((size_t)0)
#define OFF_ATTN1   ((size_t)2097152)
#define OFF_CTX2OUT ((size_t)35651584)
#define OFF_ATTN2   ((size_t)37748736)

// ---------------------------------------------------------------------------
// Batched SGEMM: C[4096,512] = A[4096,512] @ W[512,512] (+bias)
//   mode 0: row-major store; mode 1: head-major scatter; mode 2: dual q+u/q+v
// One launch covers several GEMMs; blockIdx.z picks the descriptor.
// ---------------------------------------------------------------------------
struct GDesc {
    const float* A; const float* W; const float* bias;
    float* d0; float* d1;
    const float* e0; const float* e1;
    long long mode;
};
struct GDescArr { GDesc g[8]; };

__global__ __launch_bounds__(256)
void sgemm_batch(GDescArr P)
{
    GDesc gd = P.g[blockIdx.z];
    __shared__ float As[8][128];
    __shared__ float Bs[8][128];
    int tid = threadIdx.x;
    int tx = tid & 15, ty = tid >> 4;
    int bx = blockIdx.x, by = blockIdx.y;

    ull acc[8][4];
#pragma unroll
    for (int i = 0; i < 8; i++)
#pragma unroll
        for (int j = 0; j < 4; j++) acc[i][j] = 0ull;

    int arow = tid >> 1, ahalf = tid & 1;
    int bkr = tid >> 5, bn = tid & 31;
    const float* Aptr = gd.A + (size_t)(by * 128 + arow) * 512 + ahalf * 4;
    const float* Wptr = gd.W + (size_t)bkr * 512 + bx * 128 + bn * 4;

    for (int kk = 0; kk < 64; kk++) {
        float4 av = *(const float4*)(Aptr + kk * 8);
        As[ahalf * 4 + 0][arow] = av.x;
        As[ahalf * 4 + 1][arow] = av.y;
        As[ahalf * 4 + 2][arow] = av.z;
        As[ahalf * 4 + 3][arow] = av.w;
        float4 wv = *(const float4*)(Wptr + (size_t)kk * 8 * 512);
        *(float4*)&Bs[bkr][bn * 4] = wv;
        __syncthreads();
#pragma unroll
        for (int k = 0; k < 8; k++) {
            float4 a0 = *(const float4*)&As[k][ty * 8];
            float4 a1 = *(const float4*)&As[k][ty * 8 + 4];
            float4 b0 = *(const float4*)&Bs[k][tx * 8];
            float4 b1 = *(const float4*)&Bs[k][tx * 8 + 4];
            ull bb[4] = { pk2(b0.x, b0.y), pk2(b0.z, b0.w),
                          pk2(b1.x, b1.y), pk2(b1.z, b1.w) };
            ull aa[8] = { splat2(a0.x), splat2(a0.y), splat2(a0.z), splat2(a0.w),
                          splat2(a1.x), splat2(a1.y), splat2(a1.z), splat2(a1.w) };
#pragma unroll
            for (int i = 0; i < 8; i++)
#pragma unroll
                for (int j = 0; j < 4; j++) fma2(acc[i][j], aa[i], bb[j]);
        }
        __syncthreads();
    }

    int mode = (int)gd.mode;
#pragma unroll
    for (int i = 0; i < 8; i++) {
        int gr = by * 128 + ty * 8 + i;
#pragma unroll
        for (int jj = 0; jj < 4; jj++) {
#pragma unroll
            for (int half = 0; half < 2; half++) {
                int j = 2 * jj + half;
                int gc = bx * 128 + tx * 8 + j;
                float v = (half ? hi2(acc[i][jj]) : lo2(acc[i][jj]))
                          + (gd.bias ? gd.bias[gc] : 0.f);
                if (mode == 0) {
                    gd.d0[(size_t)gr * 512 + gc] = v;
                } else {
                    int h = gc >> 6, d = gc & 63;
                    int bI = gr >> 10, sI = gr & 1023;
                    size_t off = (((size_t)(bI * Hh + h) * Ss + sI) * DHd + d);
                    if (mode == 1) {
                        gd.d0[off] = v;
                    } else {
                        gd.d0[off] = v + gd.e0[gc];
                        gd.d1[off] = v + gd.e1[gc];
                    }
                }
            }
        }
    }
}

// ---------------------------------------------------------------------------
// Fused attention kernel: per block = 16 query rows of one (b, h, stream).
// ---------------------------------------------------------------------------
__global__ __launch_bounds__(256)
void attn_kernel(float* __restrict__ scratch,
                 const unsigned char* __restrict__ maskg,
                 float* __restrict__ out)
{
    extern __shared__ float sm[];
    float* qu   = sm;                 // 16*64   = 1024 floats
    float* qv   = sm + 1024;          // 17*64   = 1088 floats
    float* kbuf = sm + 2112;          // 128*68  = 8704 floats
    float* praw = sm + 10816;         // 17*1024 = 17408 floats (reused as attn tile)
    unsigned char* msk = (unsigned char*)(sm + 28224); // 1024 bytes

    int tid = threadIdx.x;
    int lane = tid & 31, w = tid >> 5;
    int tile = blockIdx.x;   // 0..63
    int h = blockIdx.y;      // 0..7
    int bz = blockIdx.z;     // 0..7
    int b = bz >> 1, st = bz & 1;

    const float* QUg = scratch + (st ? OFF_QU2 : OFF_QU1);
    const float* QVg = scratch + (st ? OFF_QV2 : OFF_QV1);
    const float* Kg  = scratch + (st ? OFF_K2  : OFF_K1);
    const float* Vg  = scratch + (st ? OFF_V2  : OFF_V1);
    const float* Pg  = scratch + OFF_POS;
    float* CTXg = scratch + (st ? OFF_CTX2 : OFF_CTX1);

    size_t bh = (size_t)(b * Hh + h) * Ss * DHd;

    // ---- phase 0: cooperative loads ----
#pragma unroll
    for (int it = 0; it < 4; it++) {
        int idx = it * 256 + tid;                // 0..1023
        int r = idx >> 6, d = idx & 63;
        qu[idx] = QUg[bh + (size_t)(tile * 16 + r) * 64 + d];
    }
#pragma unroll
    for (int it = 0; it < 5; it++) {
        int idx = it * 256 + tid;
        if (idx < 1088) {
            int r = idx >> 6, d = idx & 63;
            int gi = tile * 16 + r;
            if (gi > Ss - 1) gi = Ss - 1;        // row 16 of last tile never used
            qv[idx] = QVg[bh + (size_t)gi * 64 + d];
        }
    }
    {
        const unsigned char* mrow = maskg + (size_t)b * Ss;
#pragma unroll
        for (int it = 0; it < 4; it++) {
            int idx = it * 256 + tid;
            msk[idx] = mrow[idx];
        }
    }
    __syncthreads();

    int r0 = 2 * w, r1 = 2 * w + 1;
    int ig0 = tile * 16 + r0, ig1 = ig0 + 1;
    float s0[32], s1[32];

    const float* kb = kbuf + lane * 68;

    // ---- phase A: content scores (q+u)·k, f32x2 packed over d ----
#pragma unroll
    for (int c = 0; c < 8; c++) {
#pragma unroll
        for (int it = 0; it < 8; it++) {
            int q = it * 256 + tid;
            int tl = q >> 4, dseg = q & 15;
            float4 vv = *(const float4*)(Kg + bh + (size_t)(c * 128 + tl) * 64 + dseg * 4);
            float* dp = kbuf + tl * 68 + dseg * 4;
            dp[0] = vv.x; dp[1] = vv.y; dp[2] = vv.z; dp[3] = vv.w;
        }
        __syncthreads();
        {
            const float* q0 = qu + r0 * 64;
            const float* q1 = qu + r1 * 64;
            ull a00 = 0, a01 = 0, a02 = 0, a03 = 0;
            ull a10 = 0, a11 = 0, a12 = 0, a13 = 0;
#pragma unroll
            for (int d4 = 0; d4 < 16; d4++) {
                ull u0a = *(const ull*)(q0 + d4 * 4);
                ull u0b = *(const ull*)(q0 + d4 * 4 + 2);
                ull u1a = *(const ull*)(q1 + d4 * 4);
                ull u1b = *(const ull*)(q1 + d4 * 4 + 2);
                ull ka, kc;
                ka = *(const ull*)(kb + 0 * 2176 + d4 * 4);
                kc = *(const ull*)(kb + 0 * 2176 + d4 * 4 + 2);
                fma2(a00, u0a, ka); fma2(a00, u0b, kc);
                fma2(a10, u1a, ka); fma2(a10, u1b, kc);
                ka = *(const ull*)(kb + 1 * 2176 + d4 * 4);
                kc = *(const ull*)(kb + 1 * 2176 + d4 * 4 + 2);
                fma2(a01, u0a, ka); fma2(a01, u0b, kc);
                fma2(a11, u1a, ka); fma2(a11, u1b, kc);
                ka = *(const ull*)(kb + 2 * 2176 + d4 * 4);
                kc = *(const ull*)(kb + 2 * 2176 + d4 * 4 + 2);
                fma2(a02, u0a, ka); fma2(a02, u0b, kc);
                fma2(a12, u1a, ka); fma2(a12, u1b, kc);
                ka = *(const ull*)(kb + 3 * 2176 + d4 * 4);
                kc = *(const ull*)(kb + 3 * 2176 + d4 * 4 + 2);
                fma2(a03, u0a, ka); fma2(a03, u0b, kc);
                fma2(a13, u1a, ka); fma2(a13, u1b, kc);
            }
            s0[c * 4 + 0] = red2(a00); s0[c * 4 + 1] = red2(a01);
            s0[c * 4 + 2] = red2(a02); s0[c * 4 + 3] = red2(a03);
            s1[c * 4 + 0] = red2(a10); s1[c * 4 + 1] = red2(a11);
            s1[c * 4 + 2] = red2(a12); s1[c * 4 + 3] = red2(a13);
        }
        __syncthreads();
    }

    // ---- phase B: pos-raw scores (q+v)·pos for 17 rows into smem ----
    // warp w computes rows 2w, 2w+1 (pairing shares pos-K loads); warp 0
    // additionally computes row 16.
#pragma unroll
    for (int c = 0; c < 8; c++) {
#pragma unroll
        for (int it = 0; it < 8; it++) {
            int q = it * 256 + tid;
            int tl = q >> 4, dseg = q & 15;
            float4 vv = *(const float4*)(Pg + bh + (size_t)(c * 128 + tl) * 64 + dseg * 4);
            float* dp = kbuf + tl * 68 + dseg * 4;
            dp[0] = vv.x; dp[1] = vv.y; dp[2] = vv.z; dp[3] = vv.w;
        }
        __syncthreads();
        {
            const float* q0 = qv + r0 * 64;
            const float* q1 = qv + r1 * 64;
            ull a00 = 0, a01 = 0, a02 = 0, a03 = 0;
            ull a10 = 0, a11 = 0, a12 = 0, a13 = 0;
#pragma unroll
            for (int d4 = 0; d4 < 16; d4++) {
                ull u0a = *(const ull*)(q0 + d4 * 4);
                ull u0b = *(const ull*)(q0 + d4 * 4 + 2);
                ull u1a = *(const ull*)(q1 + d4 * 4);
                ull u1b = *(const ull*)(q1 + d4 * 4 + 2);
                ull ka, kc;
                ka = *(const ull*)(kb + 0 * 2176 + d4 * 4);
                kc = *(const ull*)(kb + 0 * 2176 + d4 * 4 + 2);
                fma2(a00, u0a, ka); fma2(a00, u0b, kc);
                fma2(a10, u1a, ka); fma2(a10, u1b, kc);
                ka = *(const ull*)(kb + 1 * 2176 + d4 * 4);
                kc = *(const ull*)(kb + 1 * 2176 + d4 * 4 + 2);
                fma2(a01, u0a, ka); fma2(a01, u0b, kc);
                fma2(a11, u1a, ka); fma2(a11, u1b, kc);
                ka = *(const ull*)(kb + 2 * 2176 + d4 * 4);
                kc = *(const ull*)(kb + 2 * 2176 + d4 * 4 + 2);
                fma2(a02, u0a, ka); fma2(a02, u0b, kc);
                fma2(a12, u1a, ka); fma2(a12, u1b, kc);
                ka = *(const ull*)(kb + 3 * 2176 + d4 * 4);
                kc = *(const ull*)(kb + 3 * 2176 + d4 * 4 + 2);
                fma2(a03, u0a, ka); fma2(a03, u0b, kc);
                fma2(a13, u1a, ka); fma2(a13, u1b, kc);
            }
            float* pr0 = praw + r0 * 1024 + c * 128 + lane;
            float* pr1 = praw + r1 * 1024 + c * 128 + lane;
            pr0[0]  = red2(a00); pr0[32] = red2(a01);
            pr0[64] = red2(a02); pr0[96] = red2(a03);
            pr1[0]  = red2(a10); pr1[32] = red2(a11);
            pr1[64] = red2(a12); pr1[96] = red2(a13);
        }
        if (w == 0) {  // extra row 16
            const float* q2 = qv + 16 * 64;
            ull t0 = 0, t1 = 0, t2 = 0, t3 = 0;
#pragma unroll
            for (int d4 = 0; d4 < 16; d4++) {
                ull ua = *(const ull*)(q2 + d4 * 4);
                ull ub = *(const ull*)(q2 + d4 * 4 + 2);
                ull ka, kc;
                ka = *(const ull*)(kb + 0 * 2176 + d4 * 4);
                kc = *(const ull*)(kb + 0 * 2176 + d4 * 4 + 2);
                fma2(t0, ua, ka); fma2(t0, ub, kc);
                ka = *(const ull*)(kb + 1 * 2176 + d4 * 4);
                kc = *(const ull*)(kb + 1 * 2176 + d4 * 4 + 2);
                fma2(t1, ua, ka); fma2(t1, ub, kc);
                ka = *(const ull*)(kb + 2 * 2176 + d4 * 4);
                kc = *(const ull*)(kb + 2 * 2176 + d4 * 4 + 2);
                fma2(t2, ua, ka); fma2(t2, ub, kc);
                ka = *(const ull*)(kb + 3 * 2176 + d4 * 4);
                kc = *(const ull*)(kb + 3 * 2176 + d4 * 4 + 2);
                fma2(t3, ua, ka); fma2(t3, ub, kc);
            }
            float* pr = praw + 16 * 1024 + c * 128 + lane;
            pr[0] = red2(t0); pr[32] = red2(t1);
            pr[64] = red2(t2); pr[96] = red2(t3);
        }
        __syncthreads();
    }

    // ---- phase C: rel-shift gather + mask + scale + softmax ----
    float mx0 = -1e30f, mx1 = -1e30f;
#pragma unroll
    for (int jp = 0; jp < 32; jp++) {
        int t = jp * 32 + lane;
        float pv0, pv1;
        if (t <= ig0)           pv0 = praw[r0 * 1024 + (Ss - 1 - ig0 + t)];
        else if (t == ig0 + 1)  pv0 = 0.f;
        else                    pv0 = praw[(r0 + 1) * 1024 + (t - ig0 - 2)];
        if (t <= ig1)           pv1 = praw[r1 * 1024 + (Ss - 1 - ig1 + t)];
        else if (t == ig1 + 1)  pv1 = 0.f;
        else                    pv1 = praw[(r1 + 1) * 1024 + (t - ig1 - 2)];
        float sc0 = (s0[jp] + pv0) * kScale;
        float sc1 = (s1[jp] + pv1) * kScale;
        if (msk[t]) { sc0 = -1e9f; sc1 = -1e9f; }
        s0[jp] = sc0; s1[jp] = sc1;
        mx0 = fmaxf(mx0, sc0);
        mx1 = fmaxf(mx1, sc1);
    }
#pragma unroll
    for (int o = 16; o > 0; o >>= 1) {
        mx0 = fmaxf(mx0, __shfl_xor_sync(0xffffffffu, mx0, o));
        mx1 = fmaxf(mx1, __shfl_xor_sync(0xffffffffu, mx1, o));
    }
    float sum0 = 0.f, sum1 = 0.f;
#pragma unroll
    for (int jp = 0; jp < 32; jp++) {
        float e0 = __expf(s0[jp] - mx0); s0[jp] = e0; sum0 += e0;
        float e1 = __expf(s1[jp] - mx1); s1[jp] = e1; sum1 += e1;
    }
#pragma unroll
    for (int o = 16; o > 0; o >>= 1) {
        sum0 += __shfl_xor_sync(0xffffffffu, sum0, o);
        sum1 += __shfl_xor_sync(0xffffffffu, sum1, o);
    }
    float inv0 = 1.f / sum0, inv1 = 1.f / sum1;

    __syncthreads();   // all praw reads done before overwriting it with attn

    // ---- phase D: write normalized attn to gmem and smem ----
    size_t aout = (st ? OFF_ATTN2 : OFF_ATTN1) + ((size_t)(b * Hh + h) * Ss) * Ss;
#pragma unroll
    for (int jp = 0; jp < 32; jp++) {
        int t = jp * 32 + lane;
        float p0 = s0[jp] * inv0;
        float p1 = s1[jp] * inv1;
        praw[r0 * 1024 + t] = p0;
        praw[r1 * 1024 + t] = p1;
        out[aout + (size_t)ig0 * Ss + t] = p0;
        out[aout + (size_t)ig1 * Ss + t] = p1;
    }
    __syncthreads();

    // ---- phase E: ctx = attn @ V ----
    int d = tid & 63, rbase = tid >> 6;   // 64 d-lanes x 4 row-groups
    float acc[4] = {0.f, 0.f, 0.f, 0.f};
#pragma unroll
    for (int c = 0; c < 8; c++) {
#pragma unroll
        for (int it = 0; it < 8; it++) {
            int q = it * 256 + tid;
            int tl = q >> 4, dseg = q & 15;
            float4 vv = *(const float4*)(Vg + bh + (size_t)(c * 128 + tl) * 64 + dseg * 4);
            float* dp = kbuf + tl * 68 + dseg * 4;
            dp[0] = vv.x; dp[1] = vv.y; dp[2] = vv.z; dp[3] = vv.w;
        }
        __syncthreads();
#pragma unroll
        for (int t4 = 0; t4 < 32; t4++) {
            float k0 = kbuf[(t4 * 4 + 0) * 68 + d];
            float k1 = kbuf[(t4 * 4 + 1) * 68 + d];
            float k2 = kbuf[(t4 * 4 + 2) * 68 + d];
            float k3 = kbuf[(t4 * 4 + 3) * 68 + d];
#pragma unroll
            for (int rp = 0; rp < 4; rp++) {
                int row = rp * 4 + rbase;
                float4 a = *(const float4*)(praw + row * 1024 + c * 128 + t4 * 4);
                acc[rp] += a.x * k0 + a.y * k1 + a.z * k2 + a.w * k3;
            }
        }
        __syncthreads();
    }
#pragma unroll
    for (int rp = 0; rp < 4; rp++) {
        int row = rp * 4 + rbase;
        int gi = tile * 16 + row;
        CTXg[((size_t)(b * Ss + gi)) * Dd + h * DHd + d] = acc[rp];
    }
}

// ---------------------------------------------------------------------------
extern "C" void kernel_launch(void* const* d_in, const int* in_sizes, int n_in,
                              void* d_out, int out_size)
{
    const float* x1  = (const float*)d_in[0];
    const float* x2  = (const float*)d_in[1];
    const float* pe  = (const float*)d_in[2];
    const unsigned char* mask = (const unsigned char*)d_in[3];
    const float* Wq  = (const float*)d_in[4];
    const float* bq  = (const float*)d_in[5];
    const float* Wk  = (const float*)d_in[6];
    const float* bk  = (const float*)d_in[7];
    const float* Wv  = (const float*)d_in[8];
    const float* bv  = (const float*)d_in[9];
    const float* Wp  = (const float*)d_in[10];
    const float* ub  = (const float*)d_in[11];
    const float* vb  = (const float*)d_in[12];
    const float* Wo1 = (const float*)d_in[13];
    const float* bo1 = (const float*)d_in[14];
    const float* Wo2 = (const float*)d_in[15];
    const float* bo2 = (const float*)d_in[16];
    float* out = (float*)d_out;

    float* scratch = nullptr;
    cudaGetSymbolAddress((void**)&scratch, g_scratch);

    const int attn_smem = 28480 * 4;  // 113,920 B
    cudaFuncSetAttribute(attn_kernel, cudaFuncAttributeMaxDynamicSharedMemorySize,
                         attn_smem);

    // batched projections (7 GEMMs in one launch)
    GDescArr pj{};
    pj.g[0] = { x1, Wq, bq, scratch + OFF_QU1, scratch + OFF_QV1, ub, vb, 2 };
    pj.g[1] = { x1, Wk, bk, scratch + OFF_K1,  nullptr, nullptr, nullptr, 1 };
    pj.g[2] = { x1, Wv, bv, scratch + OFF_V1,  nullptr, nullptr, nullptr, 1 };
    pj.g[3] = { x2, Wq, bq, scratch + OFF_QU2, scratch + OFF_QV2, ub, vb, 2 };
    pj.g[4] = { x2, Wk, bk, scratch + OFF_K2,  nullptr, nullptr, nullptr, 1 };
    pj.g[5] = { x2, Wv, bv, scratch + OFF_V2,  nullptr, nullptr, nullptr, 1 };
    pj.g[6] = { pe, Wp, nullptr, scratch + OFF_POS, nullptr, nullptr, nullptr, 1 };
    sgemm_batch<<<dim3(4, 32, 7), 256>>>(pj);

    // fused attention: scores + rel-shift + softmax + attn-out + ctx
    attn_kernel<<<dim3(64, 8, 8), 256, attn_smem>>>(scratch, mask, out);

    // batched output projections (2 GEMMs in one launch)
    GDescArr po{};
    po.g[0] = { scratch + OFF_CTX1, Wo1, bo1, out + OFF_CTX1OUT, nullptr, nullptr, nullptr, 0 };
    po.g[1] = { scratch + OFF_CTX2, Wo2, bo2, out + OFF_CTX2OUT, nullptr, nullptr, nullptr, 0 };
    sgemm_batch<<<dim3(4, 32, 2), 256>>>(po);
}

// round 4
// speedup vs baseline: 1.2570x; 1.1303x over previous
#include <cuda_runtime.h>
#include <math.h>

#define Bb 4
#define Ss 1024
#define Dd 512
#define Hh 8
#define DHd 64

typedef unsigned long long ull;

__device__ __constant__ float kScale = 0.044194173824159216f; // 1/sqrt(512)

// ---- packed f32x2 helpers (sm_103a) ----
__device__ __forceinline__ ull pk2(float x, float y) {
    ull r; asm("mov.b64 %0, {%1, %2};" : "=l"(r) : "f"(x), "f"(y)); return r;
}
__device__ __forceinline__ ull splat2(float x) {
    ull r; asm("mov.b64 %0, {%1, %1};" : "=l"(r) : "f"(x)); return r;
}
__device__ __forceinline__ float lo2(ull v) { return __uint_as_float((unsigned)v); }
__device__ __forceinline__ float hi2(ull v) { return __uint_as_float((unsigned)(v >> 32)); }
__device__ __forceinline__ void fma2(ull& d, ull a, ull b) {
    asm("fma.rn.f32x2 %0, %1, %2, %0;" : "+l"(d) : "l"(a), "l"(b));
}
__device__ __forceinline__ float red2(ull v) { return lo2(v) + hi2(v); }

__device__ __forceinline__ unsigned smem_u32(const void* p) {
    return (unsigned)__cvta_generic_to_shared(p);
}
// one LDS.128 producing two packed f32x2 operands
__device__ __forceinline__ void lds2x64(ull& a, ull& b, unsigned addr) {
    asm("ld.shared.v2.b64 {%0,%1}, [%2];" : "=l"(a), "=l"(b) : "r"(addr));
}
__device__ __forceinline__ float lds32(unsigned addr) {
    float v; asm("ld.shared.f32 %0, [%1];" : "=f"(v) : "r"(addr)); return v;
}

// scratch: 11 chunks of B*S*D floats
#define CHUNK ((size_t)Bb * Ss * Dd)  // 2097152
__device__ float g_scratch[CHUNK * 11];

#define OFF_QU1 (0 * CHUNK)
#define OFF_QV1 (1 * CHUNK)
#define OFF_K1  (2 * CHUNK)
#define OFF_V1  (3 * CHUNK)
#define OFF_QU2 (4 * CHUNK)
#define OFF_QV2 (5 * CHUNK)
#define OFF_K2  (6 * CHUNK)
#define OFF_V2  (7 * CHUNK)
#define OFF_POS (8 * CHUNK)
#define OFF_CTX1 (9 * CHUNK)
#define OFF_CTX2 (10 * CHUNK)

// d_out offsets (floats)
#define OFF_CTX1OUT ((size_t)0)
#define OFF_ATTN1   ((size_t)2097152)
#define OFF_CTX2OUT ((size_t)35651584)
#define OFF_ATTN2   ((size_t)37748736)

// ---------------------------------------------------------------------------
// Batched SGEMM (unchanged from R3 — known good, ~390us for 7 GEMMs)
// ---------------------------------------------------------------------------
struct GDesc {
    const float* A; const float* W; const float* bias;
    float* d0; float* d1;
    const float* e0; const float* e1;
    long long mode;
};
struct GDescArr { GDesc g[8]; };

__global__ __launch_bounds__(256)
void sgemm_batch(GDescArr P)
{
    GDesc gd = P.g[blockIdx.z];
    __shared__ float As[8][128];
    __shared__ float Bs[8][128];
    int tid = threadIdx.x;
    int tx = tid & 15, ty = tid >> 4;
    int bx = blockIdx.x, by = blockIdx.y;

    ull acc[8][4];
#pragma unroll
    for (int i = 0; i < 8; i++)
#pragma unroll
        for (int j = 0; j < 4; j++) acc[i][j] = 0ull;

    int arow = tid >> 1, ahalf = tid & 1;
    int bkr = tid >> 5, bn = tid & 31;
    const float* Aptr = gd.A + (size_t)(by * 128 + arow) * 512 + ahalf * 4;
    const float* Wptr = gd.W + (size_t)bkr * 512 + bx * 128 + bn * 4;

    for (int kk = 0; kk < 64; kk++) {
        float4 av = *(const float4*)(Aptr + kk * 8);
        As[ahalf * 4 + 0][arow] = av.x;
        As[ahalf * 4 + 1][arow] = av.y;
        As[ahalf * 4 + 2][arow] = av.z;
        As[ahalf * 4 + 3][arow] = av.w;
        float4 wv = *(const float4*)(Wptr + (size_t)kk * 8 * 512);
        *(float4*)&Bs[bkr][bn * 4] = wv;
        __syncthreads();
#pragma unroll
        for (int k = 0; k < 8; k++) {
            float4 a0 = *(const float4*)&As[k][ty * 8];
            float4 a1 = *(const float4*)&As[k][ty * 8 + 4];
            float4 b0 = *(const float4*)&Bs[k][tx * 8];
            float4 b1 = *(const float4*)&Bs[k][tx * 8 + 4];
            ull bb[4] = { pk2(b0.x, b0.y), pk2(b0.z, b0.w),
                          pk2(b1.x, b1.y), pk2(b1.z, b1.w) };
            ull aa[8] = { splat2(a0.x), splat2(a0.y), splat2(a0.z), splat2(a0.w),
                          splat2(a1.x), splat2(a1.y), splat2(a1.z), splat2(a1.w) };
#pragma unroll
            for (int i = 0; i < 8; i++)
#pragma unroll
                for (int j = 0; j < 4; j++) fma2(acc[i][j], aa[i], bb[j]);
        }
        __syncthreads();
    }

    int mode = (int)gd.mode;
#pragma unroll
    for (int i = 0; i < 8; i++) {
        int gr = by * 128 + ty * 8 + i;
#pragma unroll
        for (int jj = 0; jj < 4; jj++) {
#pragma unroll
            for (int half = 0; half < 2; half++) {
                int j = 2 * jj + half;
                int gc = bx * 128 + tx * 8 + j;
                float v = (half ? hi2(acc[i][jj]) : lo2(acc[i][jj]))
                          + (gd.bias ? gd.bias[gc] : 0.f);
                if (mode == 0) {
                    gd.d0[(size_t)gr * 512 + gc] = v;
                } else {
                    int h = gc >> 6, d = gc & 63;
                    int bI = gr >> 10, sI = gr & 1023;
                    size_t off = (((size_t)(bI * Hh + h) * Ss + sI) * DHd + d);
                    if (mode == 1) {
                        gd.d0[off] = v;
                    } else {
                        gd.d0[off] = v + gd.e0[gc];
                        gd.d1[off] = v + gd.e1[gc];
                    }
                }
            }
        }
    }
}

// ---------------------------------------------------------------------------
// Score GEMM phase: out[row][col] (row<16, col<1024) = sum_d q[row][d]*k[col][d]
// Column-split mapping: warp w -> cols w*16+0..15 per 128-col tile,
// half-warp -> 8 rows each. q loads are half-warp broadcasts.
// If row16: warps 0..3 additionally compute row 16 (cols w*32+lane).
// Double-buffered tile loads (kb0/kb1).
// ---------------------------------------------------------------------------
__device__ __forceinline__ void score_gemm(
    const float* __restrict__ Gsrc, size_t bh,
    float* kb0, float* kb1, unsigned q_u,
    float* __restrict__ outp, int tid, bool row16)
{
    int lane = tid & 31, w = tid >> 5;
    int colIdx = w * 16 + (lane & 15);
    int half = lane >> 4;
    unsigned qrow_u = q_u + (unsigned)(half * 8) * 272;

    float4 fl[8];
#pragma unroll
    for (int it = 0; it < 8; it++) {
        int idx = it * 256 + tid; int s_ = idx >> 4, ds = idx & 15;
        fl[it] = *(const float4*)(Gsrc + bh + (size_t)s_ * 64 + ds * 4);
    }
#pragma unroll 1
    for (int c = 0; c < 8; c++) {
        float* kb = (c & 1) ? kb1 : kb0;
#pragma unroll
        for (int it = 0; it < 8; it++) {
            int idx = it * 256 + tid; int s_ = idx >> 4, ds = idx & 15;
            *(float4*)(kb + s_ * 68 + ds * 4) = fl[it];
        }
        __syncthreads();
        if (c < 7) {
#pragma unroll
            for (int it = 0; it < 8; it++) {
                int idx = it * 256 + tid; int s_ = idx >> 4, ds = idx & 15;
                fl[it] = *(const float4*)(Gsrc + bh
                              + (size_t)((c + 1) * 128 + s_) * 64 + ds * 4);
            }
        }
        unsigned kb_u = smem_u32(kb);
        unsigned kcol_u = kb_u + (unsigned)colIdx * 272;
        ull acc0 = 0, acc1 = 0, acc2 = 0, acc3 = 0;
        ull acc4 = 0, acc5 = 0, acc6 = 0, acc7 = 0;
#pragma unroll
        for (int dq = 0; dq < 16; dq++) {
            ull k01, k23; lds2x64(k01, k23, kcol_u + dq * 16);
            ull q01, q23;
            lds2x64(q01, q23, qrow_u + 0 * 272 + dq * 16);
            fma2(acc0, q01, k01); fma2(acc0, q23, k23);
            lds2x64(q01, q23, qrow_u + 1 * 272 + dq * 16);
            fma2(acc1, q01, k01); fma2(acc1, q23, k23);
            lds2x64(q01, q23, qrow_u + 2 * 272 + dq * 16);
            fma2(acc2, q01, k01); fma2(acc2, q23, k23);
            lds2x64(q01, q23, qrow_u + 3 * 272 + dq * 16);
            fma2(acc3, q01, k01); fma2(acc3, q23, k23);
            lds2x64(q01, q23, qrow_u + 4 * 272 + dq * 16);
            fma2(acc4, q01, k01); fma2(acc4, q23, k23);
            lds2x64(q01, q23, qrow_u + 5 * 272 + dq * 16);
            fma2(acc5, q01, k01); fma2(acc5, q23, k23);
            lds2x64(q01, q23, qrow_u + 6 * 272 + dq * 16);
            fma2(acc6, q01, k01); fma2(acc6, q23, k23);
            lds2x64(q01, q23, qrow_u + 7 * 272 + dq * 16);
            fma2(acc7, q01, k01); fma2(acc7, q23, k23);
        }
        {
            float* o = outp + (half * 8) * 1024 + c * 128 + colIdx;
            o[0 * 1024] = red2(acc0); o[1 * 1024] = red2(acc1);
            o[2 * 1024] = red2(acc2); o[3 * 1024] = red2(acc3);
            o[4 * 1024] = red2(acc4); o[5 * 1024] = red2(acc5);
            o[6 * 1024] = red2(acc6); o[7 * 1024] = red2(acc7);
        }
        if (row16 && w < 4) {
            int col16 = w * 32 + lane;
            unsigned q16_u = q_u + 16u * 272;
            unsigned kc_u = kb_u + (unsigned)col16 * 272;
            ull a = 0;
#pragma unroll
            for (int dq = 0; dq < 16; dq++) {
                ull q01, q23; lds2x64(q01, q23, q16_u + dq * 16);
                ull k01, k23; lds2x64(k01, k23, kc_u + dq * 16);
                fma2(a, q01, k01); fma2(a, q23, k23);
            }
            outp[16 * 1024 + c * 128 + col16] = red2(a);
        }
        __syncthreads();
    }
}

// ---------------------------------------------------------------------------
// Fused attention kernel: per block = 16 query rows of one (b, h, stream).
// ---------------------------------------------------------------------------
__global__ __launch_bounds__(256)
void attn_kernel(float* __restrict__ scratch,
                 const unsigned char* __restrict__ maskg,
                 float* __restrict__ out)
{
    extern __shared__ float sm[];
    float* qu   = sm;                 // [16][68]  = 1088
    float* qv   = sm + 1088;          // [17][68]  = 1156
    float* kb0  = sm + 2244;          // [128][68] = 8704
    float* kb1  = sm + 10948;         // [128][68] = 8704
    float* sbuf = sm + 19652;         // [16][1024]= 16384 (content / reduce buf)
    float* praw = sm + 36036;         // [17][1024]= 17408 (pos raw -> attn probs)
    unsigned char* msk = (unsigned char*)(sm + 53444); // 1024 B
    // total 53700 floats = 214800 B

    int tid = threadIdx.x;
    int lane = tid & 31, w = tid >> 5;
    int tile = blockIdx.x;   // 0..63
    int h = blockIdx.y;      // 0..7
    int bz = blockIdx.z;     // 0..7
    int bI = bz >> 1, st = bz & 1;

    const float* QUg = scratch + (st ? OFF_QU2 : OFF_QU1);
    const float* QVg = scratch + (st ? OFF_QV2 : OFF_QV1);
    const float* Kg  = scratch + (st ? OFF_K2  : OFF_K1);
    const float* Vg  = scratch + (st ? OFF_V2  : OFF_V1);
    const float* Pg  = scratch + OFF_POS;
    float* CTXg = scratch + (st ? OFF_CTX2 : OFF_CTX1);

    size_t bh = (size_t)(bI * Hh + h) * Ss * DHd;

    // ---- phase 0: cooperative loads of q (stride 68), mask ----
#pragma unroll
    for (int it = 0; it < 4; it++) {
        int idx = it * 256 + tid;                // 0..1023
        int r = idx >> 6, d = idx & 63;
        qu[r * 68 + d] = QUg[bh + (size_t)(tile * 16 + r) * 64 + d];
    }
#pragma unroll
    for (int it = 0; it < 5; it++) {
        int idx = it * 256 + tid;
        if (idx < 1088) {
            int r = idx >> 6, d = idx & 63;
            int gi = tile * 16 + r;
            if (gi > Ss - 1) gi = Ss - 1;        // row 16 of last tile never used
            qv[r * 68 + d] = QVg[bh + (size_t)gi * 64 + d];
        }
    }
    {
        const unsigned char* mrow = maskg + (size_t)bI * Ss;
#pragma unroll
        for (int it = 0; it < 4; it++) {
            int idx = it * 256 + tid;
            msk[idx] = mrow[idx];
        }
    }
    __syncthreads();

    unsigned qu_u = smem_u32(qu);
    unsigned qv_u = smem_u32(qv);

    // ---- phase A: content scores -> sbuf ----
    score_gemm(Kg, bh, kb0, kb1, qu_u, sbuf, tid, false);
    // ---- phase B: pos raw scores (17 rows) -> praw ----
    score_gemm(Pg, bh, kb0, kb1, qv_u, praw, tid, true);

    // ---- phase C: rel-shift gather + mask + scale + softmax (warp = 2 rows) ----
    int r0 = 2 * w, r1 = 2 * w + 1;
    int ig0 = tile * 16 + r0, ig1 = ig0 + 1;
    float s0[32], s1[32];

    float mx0 = -1e30f, mx1 = -1e30f;
#pragma unroll
    for (int jp = 0; jp < 32; jp++) {
        int t = jp * 32 + lane;
        float pv0, pv1;
        if (t <= ig0)           pv0 = praw[r0 * 1024 + (Ss - 1 - ig0 + t)];
        else if (t == ig0 + 1)  pv0 = 0.f;
        else                    pv0 = praw[(r0 + 1) * 1024 + (t - ig0 - 2)];
        if (t <= ig1)           pv1 = praw[r1 * 1024 + (Ss - 1 - ig1 + t)];
        else if (t == ig1 + 1)  pv1 = 0.f;
        else                    pv1 = praw[(r1 + 1) * 1024 + (t - ig1 - 2)];
        float sc0 = (sbuf[r0 * 1024 + t] + pv0) * kScale;
        float sc1 = (sbuf[r1 * 1024 + t] + pv1) * kScale;
        if (msk[t]) { sc0 = -1e9f; sc1 = -1e9f; }
        s0[jp] = sc0; s1[jp] = sc1;
        mx0 = fmaxf(mx0, sc0);
        mx1 = fmaxf(mx1, sc1);
    }
#pragma unroll
    for (int o = 16; o > 0; o >>= 1) {
        mx0 = fmaxf(mx0, __shfl_xor_sync(0xffffffffu, mx0, o));
        mx1 = fmaxf(mx1, __shfl_xor_sync(0xffffffffu, mx1, o));
    }
    float sum0 = 0.f, sum1 = 0.f;
#pragma unroll
    for (int jp = 0; jp < 32; jp++) {
        float e0 = __expf(s0[jp] - mx0); s0[jp] = e0; sum0 += e0;
        float e1 = __expf(s1[jp] - mx1); s1[jp] = e1; sum1 += e1;
    }
#pragma unroll
    for (int o = 16; o > 0; o >>= 1) {
        sum0 += __shfl_xor_sync(0xffffffffu, sum0, o);
        sum1 += __shfl_xor_sync(0xffffffffu, sum1, o);
    }
    float inv0 = 1.f / sum0, inv1 = 1.f / sum1;

    __syncthreads();   // all praw/sbuf reads done before overwriting praw

    // ---- phase D: write normalized attn to gmem and praw ----
    size_t aout = (st ? OFF_ATTN2 : OFF_ATTN1) + ((size_t)(bI * Hh + h) * Ss) * Ss;
#pragma unroll
    for (int jp = 0; jp < 32; jp++) {
        int t = jp * 32 + lane;
        float p0 = s0[jp] * inv0;
        float p1 = s1[jp] * inv1;
        praw[r0 * 1024 + t] = p0;
        praw[r1 * 1024 + t] = p1;
        out[aout + (size_t)ig0 * Ss + t] = p0;
        out[aout + (size_t)ig1 * Ss + t] = p1;
    }
    __syncthreads();

    // ---- phase E: ctx = attn @ V, f32x2 over d, t split 4-way ----
    {
        int dpg = tid & 15;        // d0 = dpg*4 (4 d-values, 2 f32x2 pairs)
        int rg  = (tid >> 4) & 3;  // rows rg*4 .. rg*4+3
        int tq  = tid >> 6;        // t-quarter within each 128-col tile
        int d0 = dpg * 4;

        ull e00 = 0, e01 = 0, e10 = 0, e11 = 0;
        ull e20 = 0, e21 = 0, e30 = 0, e31 = 0;

        float4 fl[8];
#pragma unroll
        for (int it = 0; it < 8; it++) {
            int idx = it * 256 + tid; int s_ = idx >> 4, ds = idx & 15;
            fl[it] = *(const float4*)(Vg + bh + (size_t)s_ * 64 + ds * 4);
        }
        unsigned pr_base = smem_u32(praw) + (unsigned)(rg * 4 * 1024 + tq * 32) * 4;
#pragma unroll 1
        for (int c = 0; c < 8; c++) {
            float* kb = (c & 1) ? kb1 : kb0;
#pragma unroll
            for (int it = 0; it < 8; it++) {
                int idx = it * 256 + tid; int s_ = idx >> 4, ds = idx & 15;
                *(float4*)(kb + s_ * 68 + ds * 4) = fl[it];
            }
            __syncthreads();
            if (c < 7) {
#pragma unroll
                for (int it = 0; it < 8; it++) {
                    int idx = it * 256 + tid; int s_ = idx >> 4, ds = idx & 15;
                    fl[it] = *(const float4*)(Vg + bh
                                  + (size_t)((c + 1) * 128 + s_) * 64 + ds * 4);
                }
            }
            unsigned v_base = smem_u32(kb) + (unsigned)(tq * 32) * 272 + d0 * 4;
            unsigned pr_u = pr_base + (unsigned)(c * 128) * 4;
#pragma unroll
            for (int tt = 0; tt < 32; tt++) {
                ull v01, v23; lds2x64(v01, v23, v_base + tt * 272);
                float a0 = lds32(pr_u + tt * 4 + 0 * 4096);
                float a1 = lds32(pr_u + tt * 4 + 1 * 4096);
                float a2 = lds32(pr_u + tt * 4 + 2 * 4096);
                float a3 = lds32(pr_u + tt * 4 + 3 * 4096);
                ull s;
                s = splat2(a0); fma2(e00, s, v01); fma2(e01, s, v23);
                s = splat2(a1); fma2(e10, s, v01); fma2(e11, s, v23);
                s = splat2(a2); fma2(e20, s, v01); fma2(e21, s, v23);
                s = splat2(a3); fma2(e30, s, v01); fma2(e31, s, v23);
            }
            __syncthreads();
        }

        // partial sums -> sbuf[tq][row*64+d], then reduce 4 quarters
        {
            float* red = sbuf + tq * 1024 + (rg * 4) * 64 + d0;
            red[0 * 64 + 0] = lo2(e00); red[0 * 64 + 1] = hi2(e00);
            red[0 * 64 + 2] = lo2(e01); red[0 * 64 + 3] = hi2(e01);
            red[1 * 64 + 0] = lo2(e10); red[1 * 64 + 1] = hi2(e10);
            red[1 * 64 + 2] = lo2(e11); red[1 * 64 + 3] = hi2(e11);
            red[2 * 64 + 0] = lo2(e20); red[2 * 64 + 1] = hi2(e20);
            red[2 * 64 + 2] = lo2(e21); red[2 * 64 + 3] = hi2(e21);
            red[3 * 64 + 0] = lo2(e30); red[3 * 64 + 1] = hi2(e30);
            red[3 * 64 + 2] = lo2(e31); red[3 * 64 + 3] = hi2(e31);
        }
        __syncthreads();
        {
            int o = tid * 4;                  // 0..1023, 4 outputs per thread
            int row = o >> 6, dd = o & 63;
            float4 p0 = *(const float4*)(sbuf + 0 * 1024 + o);
            float4 p1 = *(const float4*)(sbuf + 1 * 1024 + o);
            float4 p2 = *(const float4*)(sbuf + 2 * 1024 + o);
            float4 p3 = *(const float4*)(sbuf + 3 * 1024 + o);
            float4 r;
            r.x = (p0.x + p1.x) + (p2.x + p3.x);
            r.y = (p0.y + p1.y) + (p2.y + p3.y);
            r.z = (p0.z + p1.z) + (p2.z + p3.z);
            r.w = (p0.w + p1.w) + (p2.w + p3.w);
            int gi = tile * 16 + row;
            *(float4*)(CTXg + ((size_t)(bI * Ss + gi)) * Dd + h * DHd + dd) = r;
        }
    }
}

// ---------------------------------------------------------------------------
extern "C" void kernel_launch(void* const* d_in, const int* in_sizes, int n_in,
                              void* d_out, int out_size)
{
    const float* x1  = (const float*)d_in[0];
    const float* x2  = (const float*)d_in[1];
    const float* pe  = (const float*)d_in[2];
    const unsigned char* mask = (const unsigned char*)d_in[3];
    const float* Wq  = (const float*)d_in[4];
    const float* bq  = (const float*)d_in[5];
    const float* Wk  = (const float*)d_in[6];
    const float* bk  = (const float*)d_in[7];
    const float* Wv  = (const float*)d_in[8];
    const float* bv  = (const float*)d_in[9];
    const float* Wp  = (const float*)d_in[10];
    const float* ub  = (const float*)d_in[11];
    const float* vb  = (const float*)d_in[12];
    const float* Wo1 = (const float*)d_in[13];
    const float* bo1 = (const float*)d_in[14];
    const float* Wo2 = (const float*)d_in[15];
    const float* bo2 = (const float*)d_in[16];
    float* out = (float*)d_out;

    float* scratch = nullptr;
    cudaGetSymbolAddress((void**)&scratch, g_scratch);

    const int attn_smem = 53700 * 4;  // 214,800 B
    cudaFuncSetAttribute(attn_kernel, cudaFuncAttributeMaxDynamicSharedMemorySize,
                         attn_smem);

    // batched projections (7 GEMMs in one launch)
    GDescArr pj{};
    pj.g[0] = { x1, Wq, bq, scratch + OFF_QU1, scratch + OFF_QV1, ub, vb, 2 };
    pj.g[1] = { x1, Wk, bk, scratch + OFF_K1,  nullptr, nullptr, nullptr, 1 };
    pj.g[2] = { x1, Wv, bv, scratch + OFF_V1,  nullptr, nullptr, nullptr, 1 };
    pj.g[3] = { x2, Wq, bq, scratch + OFF_QU2, scratch + OFF_QV2, ub, vb, 2 };
    pj.g[4] = { x2, Wk, bk, scratch + OFF_K2,  nullptr, nullptr, nullptr, 1 };
    pj.g[5] = { x2, Wv, bv, scratch + OFF_V2,  nullptr, nullptr, nullptr, 1 };
    pj.g[6] = { pe, Wp, nullptr, scratch + OFF_POS, nullptr, nullptr, nullptr, 1 };
    sgemm_batch<<<dim3(4, 32, 7), 256>>>(pj);

    // fused attention: scores + rel-shift + softmax + attn-out + ctx
    attn_kernel<<<dim3(64, 8, 8), 256, attn_smem>>>(scratch, mask, out);

    // batched output projections (2 GEMMs in one launch)
    GDescArr po{};
    po.g[0] = { scratch + OFF_CTX1, Wo1, bo1, out + OFF_CTX1OUT, nullptr, nullptr, nullptr, 0 };
    po.g[1] = { scratch + OFF_CTX2, Wo2, bo2, out + OFF_CTX2OUT, nullptr, nullptr, nullptr, 0 };
    sgemm_batch<<<dim3(4, 32, 2), 256>>>(po);
}

// round 5
// speedup vs baseline: 1.9533x; 1.5539x over previous
#include <cuda_runtime.h>
#include <math.h>

#define Bb 4
#define Ss 1024
#define Dd 512
#define Hh 8
#define DHd 64

typedef unsigned long long ull;

__device__ __constant__ float kScale = 0.044194173824159216f; // 1/sqrt(512)

// ---- packed f32x2 helpers (sm_103a) ----
__device__ __forceinline__ ull pk2(float x, float y) {
    ull r; asm("mov.b64 %0, {%1, %2};" : "=l"(r) : "f"(x), "f"(y)); return r;
}
__device__ __forceinline__ ull splat2(float x) {
    ull r; asm("mov.b64 %0, {%1, %1};" : "=l"(r) : "f"(x)); return r;
}
__device__ __forceinline__ float lo2(ull v) { return __uint_as_float((unsigned)v); }
__device__ __forceinline__ float hi2(ull v) { return __uint_as_float((unsigned)(v >> 32)); }
__device__ __forceinline__ void fma2(ull& d, ull a, ull b) {
    asm("fma.rn.f32x2 %0, %1, %2, %0;" : "+l"(d) : "l"(a), "l"(b));
}
__device__ __forceinline__ float red2(ull v) { return lo2(v) + hi2(v); }

__device__ __forceinline__ unsigned smem_u32(const void* p) {
    return (unsigned)__cvta_generic_to_shared(p);
}
// one LDS.128 producing two packed f32x2 operands
__device__ __forceinline__ void lds2x64(ull& a, ull& b, unsigned addr) {
    asm("ld.shared.v2.b64 {%0,%1}, [%2];" : "=l"(a), "=l"(b) : "r"(addr));
}
__device__ __forceinline__ float lds32(unsigned addr) {
    float v; asm("ld.shared.f32 %0, [%1];" : "=f"(v) : "r"(addr)); return v;
}

// scratch: 11 chunks of B*S*D floats
#define CHUNK ((size_t)Bb * Ss * Dd)  // 2097152
__device__ float g_scratch[CHUNK * 11];

#define OFF_QU1 (0 * CHUNK)
#define OFF_QV1 (1 * CHUNK)
#define OFF_K1  (2 * CHUNK)
#define OFF_V1  (3 * CHUNK)
#define OFF_QU2 (4 * CHUNK)
#define OFF_QV2 (5 * CHUNK)
#define OFF_K2  (6 * CHUNK)
#define OFF_V2  (7 * CHUNK)
#define OFF_POS (8 * CHUNK)
#define OFF_CTX1 (9 * CHUNK)
#define OFF_CTX2 (10 * CHUNK)

// d_out offsets (floats)
#define OFF_CTX1OUT ((size_t)0)
#define OFF_ATTN1   ((size_t)2097152)
#define OFF_CTX2OUT ((size_t)35651584)
#define OFF_ATTN2   ((size_t)37748736)

// ---------------------------------------------------------------------------
// Batched SGEMM: C[4096,512] = A[4096,512] @ W[512,512] (+bias)
// Double-buffered smem, register prefetch, one barrier per k-slice.
// ---------------------------------------------------------------------------
struct GDesc {
    const float* A; const float* W; const float* bias;
    float* d0; float* d1;
    const float* e0; const float* e1;
    long long mode;
};
struct GDescArr { GDesc g[8]; };

__global__ __launch_bounds__(256, 2)
void sgemm_batch(GDescArr P)
{
    GDesc gd = P.g[blockIdx.z];
    __shared__ float As[2][8][128];
    __shared__ float Bs[2][8][128];
    int tid = threadIdx.x;
    int tx = tid & 15, ty = tid >> 4;
    int bx = blockIdx.x, by = blockIdx.y;

    ull acc[8][4];
#pragma unroll
    for (int i = 0; i < 8; i++)
#pragma unroll
        for (int j = 0; j < 4; j++) acc[i][j] = 0ull;

    int arow = tid >> 1, ahalf = tid & 1;
    int bkr = tid >> 5, bn = tid & 31;
    const float* Aptr = gd.A + (size_t)(by * 128 + arow) * 512 + ahalf * 4;
    const float* Wptr = gd.W + (size_t)bkr * 512 + bx * 128 + bn * 4;

    // prefetch k-slice 0 and stage into buffer 0
    float4 av = *(const float4*)(Aptr);
    float4 wv = *(const float4*)(Wptr);
    As[0][ahalf * 4 + 0][arow] = av.x;
    As[0][ahalf * 4 + 1][arow] = av.y;
    As[0][ahalf * 4 + 2][arow] = av.z;
    As[0][ahalf * 4 + 3][arow] = av.w;
    *(float4*)&Bs[0][bkr][bn * 4] = wv;
    __syncthreads();

#pragma unroll 1
    for (int kk = 0; kk < 64; kk++) {
        int buf = kk & 1;
        if (kk < 63) {
            av = *(const float4*)(Aptr + (kk + 1) * 8);
            wv = *(const float4*)(Wptr + (size_t)(kk + 1) * 8 * 512);
        }
#pragma unroll
        for (int k = 0; k < 8; k++) {
            float4 a0 = *(const float4*)&As[buf][k][ty * 8];
            float4 a1 = *(const float4*)&As[buf][k][ty * 8 + 4];
            unsigned bs_u = smem_u32(&Bs[buf][k][tx * 8]);
            ull bb[4];
            lds2x64(bb[0], bb[1], bs_u);
            lds2x64(bb[2], bb[3], bs_u + 16);
            ull aa[8] = { splat2(a0.x), splat2(a0.y), splat2(a0.z), splat2(a0.w),
                          splat2(a1.x), splat2(a1.y), splat2(a1.z), splat2(a1.w) };
#pragma unroll
            for (int i = 0; i < 8; i++)
#pragma unroll
                for (int j = 0; j < 4; j++) fma2(acc[i][j], aa[i], bb[j]);
        }
        if (kk < 63) {
            int nb = buf ^ 1;
            As[nb][ahalf * 4 + 0][arow] = av.x;
            As[nb][ahalf * 4 + 1][arow] = av.y;
            As[nb][ahalf * 4 + 2][arow] = av.z;
            As[nb][ahalf * 4 + 3][arow] = av.w;
            *(float4*)&Bs[nb][bkr][bn * 4] = wv;
            __syncthreads();
        }
    }

    int mode = (int)gd.mode;
#pragma unroll
    for (int i = 0; i < 8; i++) {
        int gr = by * 128 + ty * 8 + i;
#pragma unroll
        for (int jj = 0; jj < 4; jj++) {
#pragma unroll
            for (int half = 0; half < 2; half++) {
                int j = 2 * jj + half;
                int gc = bx * 128 + tx * 8 + j;
                float v = (half ? hi2(acc[i][jj]) : lo2(acc[i][jj]))
                          + (gd.bias ? gd.bias[gc] : 0.f);
                if (mode == 0) {
                    gd.d0[(size_t)gr * 512 + gc] = v;
                } else {
                    int h = gc >> 6, d = gc & 63;
                    int bI = gr >> 10, sI = gr & 1023;
                    size_t off = (((size_t)(bI * Hh + h) * Ss + sI) * DHd + d);
                    if (mode == 1) {
                        gd.d0[off] = v;
                    } else {
                        gd.d0[off] = v + gd.e0[gc];
                        gd.d1[off] = v + gd.e1[gc];
                    }
                }
            }
        }
    }
}

// ---------------------------------------------------------------------------
// Score GEMM (512 threads): out[row][col] = sum_d q[row][d]*k[col][d]
// warp w -> 8 cols per 128-col tile; lane quarter -> 4 rows each.
// If row16: warps 0..3 additionally compute row 16 (cols w*32+lane).
// Double-buffered tile loads.
// ---------------------------------------------------------------------------
__device__ __forceinline__ void score_gemm512(
    const float* __restrict__ Gsrc, size_t bh,
    float* kb0, float* kb1, unsigned q_u,
    float* __restrict__ outp, int tid, bool row16)
{
    int lane = tid & 31, w = tid >> 5;          // w 0..15
    int colIdx = w * 8 + (lane & 7);
    int qt = lane >> 3;                          // quarter 0..3 -> rows qt*4..+3
    unsigned qrow_u = q_u + (unsigned)(qt * 4) * 272;

    float4 fl[4];
#pragma unroll
    for (int it = 0; it < 4; it++) {
        int idx = it * 512 + tid; int s_ = idx >> 4, ds = idx & 15;
        fl[it] = *(const float4*)(Gsrc + bh + (size_t)s_ * 64 + ds * 4);
    }
#pragma unroll 1
    for (int c = 0; c < 8; c++) {
        float* kb = (c & 1) ? kb1 : kb0;
#pragma unroll
        for (int it = 0; it < 4; it++) {
            int idx = it * 512 + tid; int s_ = idx >> 4, ds = idx & 15;
            *(float4*)(kb + s_ * 68 + ds * 4) = fl[it];
        }
        __syncthreads();
        if (c < 7) {
#pragma unroll
            for (int it = 0; it < 4; it++) {
                int idx = it * 512 + tid; int s_ = idx >> 4, ds = idx & 15;
                fl[it] = *(const float4*)(Gsrc + bh
                              + (size_t)((c + 1) * 128 + s_) * 64 + ds * 4);
            }
        }
        unsigned kb_u = smem_u32(kb);
        unsigned kcol_u = kb_u + (unsigned)colIdx * 272;
        ull acc0 = 0, acc1 = 0, acc2 = 0, acc3 = 0;
#pragma unroll
        for (int dq = 0; dq < 16; dq++) {
            ull k01, k23; lds2x64(k01, k23, kcol_u + dq * 16);
            ull q01, q23;
            lds2x64(q01, q23, qrow_u + 0 * 272 + dq * 16);
            fma2(acc0, q01, k01); fma2(acc0, q23, k23);
            lds2x64(q01, q23, qrow_u + 1 * 272 + dq * 16);
            fma2(acc1, q01, k01); fma2(acc1, q23, k23);
            lds2x64(q01, q23, qrow_u + 2 * 272 + dq * 16);
            fma2(acc2, q01, k01); fma2(acc2, q23, k23);
            lds2x64(q01, q23, qrow_u + 3 * 272 + dq * 16);
            fma2(acc3, q01, k01); fma2(acc3, q23, k23);
        }
        {
            float* o = outp + (qt * 4) * 1024 + c * 128 + colIdx;
            o[0 * 1024] = red2(acc0); o[1 * 1024] = red2(acc1);
            o[2 * 1024] = red2(acc2); o[3 * 1024] = red2(acc3);
        }
        if (row16 && w < 4) {
            int col16 = w * 32 + lane;
            unsigned q16_u = q_u + 16u * 272;
            unsigned kc_u = kb_u + (unsigned)col16 * 272;
            ull a = 0;
#pragma unroll
            for (int dq = 0; dq < 16; dq++) {
                ull q01, q23; lds2x64(q01, q23, q16_u + dq * 16);
                ull k01, k23; lds2x64(k01, k23, kc_u + dq * 16);
                fma2(a, q01, k01); fma2(a, q23, k23);
            }
            outp[16 * 1024 + c * 128 + col16] = red2(a);
        }
        __syncthreads();
    }
}

// ---------------------------------------------------------------------------
// Fused attention kernel (512 threads): per block = 16 q-rows of (b,h,stream).
// ---------------------------------------------------------------------------
__global__ __launch_bounds__(512)
void attn_kernel(float* __restrict__ scratch,
                 const unsigned char* __restrict__ maskg,
                 float* __restrict__ out)
{
    extern __shared__ float sm[];
    float* qu   = sm;                 // [16][68]  = 1088
    float* qv   = sm + 1088;          // [17][68]  = 1156
    float* kb0  = sm + 2244;          // [128][68] = 8704
    float* kb1  = sm + 10948;         // [128][68] = 8704
    float* sbuf = sm + 19652;         // [16][1024]= 16384 (content / reduce buf)
    float* praw = sm + 36036;         // [17][1024]= 17408 (pos raw -> attn probs)
    unsigned char* msk = (unsigned char*)(sm + 53444); // 1024 B

    int tid = threadIdx.x;
    int lane = tid & 31, w = tid >> 5;   // w 0..15
    int tile = blockIdx.x;   // 0..63
    int h = blockIdx.y;      // 0..7
    int bz = blockIdx.z;     // 0..7
    int bI = bz >> 1, st = bz & 1;

    const float* QUg = scratch + (st ? OFF_QU2 : OFF_QU1);
    const float* QVg = scratch + (st ? OFF_QV2 : OFF_QV1);
    const float* Kg  = scratch + (st ? OFF_K2  : OFF_K1);
    const float* Vg  = scratch + (st ? OFF_V2  : OFF_V1);
    const float* Pg  = scratch + OFF_POS;
    float* CTXg = scratch + (st ? OFF_CTX2 : OFF_CTX1);

    size_t bh = (size_t)(bI * Hh + h) * Ss * DHd;

    // ---- phase 0: cooperative loads of q (stride 68), mask ----
#pragma unroll
    for (int it = 0; it < 2; it++) {
        int idx = it * 512 + tid;                // 0..1023
        int r = idx >> 6, d = idx & 63;
        qu[r * 68 + d] = QUg[bh + (size_t)(tile * 16 + r) * 64 + d];
    }
#pragma unroll
    for (int it = 0; it < 3; it++) {
        int idx = it * 512 + tid;
        if (idx < 1088) {
            int r = idx >> 6, d = idx & 63;
            int gi = tile * 16 + r;
            if (gi > Ss - 1) gi = Ss - 1;        // row 16 of last tile never used
            qv[r * 68 + d] = QVg[bh + (size_t)gi * 64 + d];
        }
    }
    {
        const unsigned char* mrow = maskg + (size_t)bI * Ss;
#pragma unroll
        for (int it = 0; it < 2; it++) {
            int idx = it * 512 + tid;
            msk[idx] = mrow[idx];
        }
    }
    __syncthreads();

    unsigned qu_u = smem_u32(qu);
    unsigned qv_u = smem_u32(qv);

    // ---- phase A: content scores -> sbuf ----
    score_gemm512(Kg, bh, kb0, kb1, qu_u, sbuf, tid, false);
    // ---- phase B: pos raw scores (17 rows) -> praw ----
    score_gemm512(Pg, bh, kb0, kb1, qv_u, praw, tid, true);

    // ---- phase C: rel-shift gather + mask + scale + softmax (warp = 1 row) ----
    int r = w;
    int ig = tile * 16 + r;
    float s[32];

    float mx = -1e30f;
#pragma unroll
    for (int jp = 0; jp < 32; jp++) {
        int t = jp * 32 + lane;
        float pv;
        if (t <= ig)           pv = praw[r * 1024 + (Ss - 1 - ig + t)];
        else if (t == ig + 1)  pv = 0.f;
        else                   pv = praw[(r + 1) * 1024 + (t - ig - 2)];
        float sc = (sbuf[r * 1024 + t] + pv) * kScale;
        if (msk[t]) sc = -1e9f;
        s[jp] = sc;
        mx = fmaxf(mx, sc);
    }
#pragma unroll
    for (int o = 16; o > 0; o >>= 1)
        mx = fmaxf(mx, __shfl_xor_sync(0xffffffffu, mx, o));
    float sum = 0.f;
#pragma unroll
    for (int jp = 0; jp < 32; jp++) {
        float e = __expf(s[jp] - mx); s[jp] = e; sum += e;
    }
#pragma unroll
    for (int o = 16; o > 0; o >>= 1)
        sum += __shfl_xor_sync(0xffffffffu, sum, o);
    float inv = 1.f / sum;

    __syncthreads();   // all praw/sbuf reads done before overwriting praw

    // ---- phase D: write normalized attn to gmem and praw ----
    size_t aout = (st ? OFF_ATTN2 : OFF_ATTN1) + ((size_t)(bI * Hh + h) * Ss) * Ss;
#pragma unroll
    for (int jp = 0; jp < 32; jp++) {
        int t = jp * 32 + lane;
        float p = s[jp] * inv;
        praw[r * 1024 + t] = p;
        out[aout + (size_t)ig * Ss + t] = p;
    }
    __syncthreads();

    // ---- phase E: ctx = attn @ V, f32x2 over d, rows 8-way, t 4-way ----
    {
        int dpg = tid & 15;        // d0 = dpg*4
        int rg  = (tid >> 4) & 7;  // rows rg*2, rg*2+1
        int tq  = tid >> 7;        // t-quarter 0..3
        int d0 = dpg * 4;

        ull e00 = 0, e01 = 0, e10 = 0, e11 = 0;

        float4 fl[4];
#pragma unroll
        for (int it = 0; it < 4; it++) {
            int idx = it * 512 + tid; int s_ = idx >> 4, ds = idx & 15;
            fl[it] = *(const float4*)(Vg + bh + (size_t)s_ * 64 + ds * 4);
        }
        unsigned pr_base = smem_u32(praw) + (unsigned)(rg * 2 * 1024 + tq * 32) * 4;
#pragma unroll 1
        for (int c = 0; c < 8; c++) {
            float* kb = (c & 1) ? kb1 : kb0;
#pragma unroll
            for (int it = 0; it < 4; it++) {
                int idx = it * 512 + tid; int s_ = idx >> 4, ds = idx & 15;
                *(float4*)(kb + s_ * 68 + ds * 4) = fl[it];
            }
            __syncthreads();
            if (c < 7) {
#pragma unroll
                for (int it = 0; it < 4; it++) {
                    int idx = it * 512 + tid; int s_ = idx >> 4, ds = idx & 15;
                    fl[it] = *(const float4*)(Vg + bh
                                  + (size_t)((c + 1) * 128 + s_) * 64 + ds * 4);
                }
            }
            unsigned v_base = smem_u32(kb) + (unsigned)(tq * 32) * 272 + d0 * 4;
            unsigned pr_u = pr_base + (unsigned)(c * 128) * 4;
#pragma unroll
            for (int tt = 0; tt < 32; tt++) {
                ull v01, v23; lds2x64(v01, v23, v_base + tt * 272);
                float a0 = lds32(pr_u + tt * 4 + 0 * 4096);
                float a1 = lds32(pr_u + tt * 4 + 1 * 4096);
                ull sx;
                sx = splat2(a0); fma2(e00, sx, v01); fma2(e01, sx, v23);
                sx = splat2(a1); fma2(e10, sx, v01); fma2(e11, sx, v23);
            }
            __syncthreads();
        }

        // partial sums -> sbuf[tq][row*64+d], then reduce 4 quarters
        {
            float* red = sbuf + tq * 1024 + (rg * 2) * 64 + d0;
            float4 v0; v0.x = lo2(e00); v0.y = hi2(e00); v0.z = lo2(e01); v0.w = hi2(e01);
            float4 v1; v1.x = lo2(e10); v1.y = hi2(e10); v1.z = lo2(e11); v1.w = hi2(e11);
            *(float4*)(red) = v0;
            *(float4*)(red + 64) = v1;
        }
        __syncthreads();
        if (tid < 256) {
            int o = tid * 4;                  // 0..1023, 4 outputs per thread
            int row = o >> 6, dd = o & 63;
            float4 p0 = *(const float4*)(sbuf + 0 * 1024 + o);
            float4 p1 = *(const float4*)(sbuf + 1 * 1024 + o);
            float4 p2 = *(const float4*)(sbuf + 2 * 1024 + o);
            float4 p3 = *(const float4*)(sbuf + 3 * 1024 + o);
            float4 rr;
            rr.x = (p0.x + p1.x) + (p2.x + p3.x);
            rr.y = (p0.y + p1.y) + (p2.y + p3.y);
            rr.z = (p0.z + p1.z) + (p2.z + p3.z);
            rr.w = (p0.w + p1.w) + (p2.w + p3.w);
            int gi = tile * 16 + row;
            *(float4*)(CTXg + ((size_t)(bI * Ss + gi)) * Dd + h * DHd + dd) = rr;
        }
    }
}

// ---------------------------------------------------------------------------
extern "C" void kernel_launch(void* const* d_in, const int* in_sizes, int n_in,
                              void* d_out, int out_size)
{
    const float* x1  = (const float*)d_in[0];
    const float* x2  = (const float*)d_in[1];
    const float* pe  = (const float*)d_in[2];
    const unsigned char* mask = (const unsigned char*)d_in[3];
    const float* Wq  = (const float*)d_in[4];
    const float* bq  = (const float*)d_in[5];
    const float* Wk  = (const float*)d_in[6];
    const float* bk  = (const float*)d_in[7];
    const float* Wv  = (const float*)d_in[8];
    const float* bv  = (const float*)d_in[9];
    const float* Wp  = (const float*)d_in[10];
    const float* ub  = (const float*)d_in[11];
    const float* vb  = (const float*)d_in[12];
    const float* Wo1 = (const float*)d_in[13];
    const float* bo1 = (const float*)d_in[14];
    const float* Wo2 = (const float*)d_in[15];
    const float* bo2 = (const float*)d_in[16];
    float* out = (float*)d_out;

    float* scratch = nullptr;
    cudaGetSymbolAddress((void**)&scratch, g_scratch);

    const int attn_smem = 53700 * 4;  // 214,800 B
    cudaFuncSetAttribute(attn_kernel, cudaFuncAttributeMaxDynamicSharedMemorySize,
                         attn_smem);

    // batched projections (7 GEMMs in one launch)
    GDescArr pj{};
    pj.g[0] = { x1, Wq, bq, scratch + OFF_QU1, scratch + OFF_QV1, ub, vb, 2 };
    pj.g[1] = { x1, Wk, bk, scratch + OFF_K1,  nullptr, nullptr, nullptr, 1 };
    pj.g[2] = { x1, Wv, bv, scratch + OFF_V1,  nullptr, nullptr, nullptr, 1 };
    pj.g[3] = { x2, Wq, bq, scratch + OFF_QU2, scratch + OFF_QV2, ub, vb, 2 };
    pj.g[4] = { x2, Wk, bk, scratch + OFF_K2,  nullptr, nullptr, nullptr, 1 };
    pj.g[5] = { x2, Wv, bv, scratch + OFF_V2,  nullptr, nullptr, nullptr, 1 };
    pj.g[6] = { pe, Wp, nullptr, scratch + OFF_POS, nullptr, nullptr, nullptr, 1 };
    sgemm_batch<<<dim3(4, 32, 7), 256>>>(pj);

    // fused attention: scores + rel-shift + softmax + attn-out + ctx
    attn_kernel<<<dim3(64, 8, 8), 512, attn_smem>>>(scratch, mask, out);

    // batched output projections (2 GEMMs in one launch)
    GDescArr po{};
    po.g[0] = { scratch + OFF_CTX1, Wo1, bo1, out + OFF_CTX1OUT, nullptr, nullptr, nullptr, 0 };
    po.g[1] = { scratch + OFF_CTX2, Wo2, bo2, out + OFF_CTX2OUT, nullptr, nullptr, nullptr, 0 };
    sgemm_batch<<<dim3(4, 32, 2), 256>>>(po);
}